// round 7
// baseline (speedup 1.0000x reference)
#include <cuda_runtime.h>
#include <cuda_bf16.h>
#include <math.h>

// ---------------- problem constants ----------------
#define STEPS 20000
#define NCOL  2048
#define NCOL4 (NCOL/4)      // 512 column-groups
#define CH    50            // steps per chunk
#define NCH   (STEPS/CH)    // 400 chunks
#define NWORK (NCH * NCOL)  // per-(chunk,col) scratch entries
#define NTHRD (NCH * NCOL4) // chunk-threads (each owns 4 cols)
#define NBINS 200000
#define HISTN (NBINS + 1)

#define R1_SUM_D 123020000.0
__device__ __constant__ float c_invr[4] = {
    1.0f / 1.0e6f, (float)(1.0 / R1_SUM_D), 1.0f / 1.0e5f, (float)(1.0 / 0.2)
};

__device__ __forceinline__ void get_thresholds(float& A, float& B, float& C) {
    const double c0 = 50000000.0 / R1_SUM_D;
    const double c2 = c0 + 3000000.0 / R1_SUM_D;
    const double c3 = c2 + 20000.0 / R1_SUM_D;
    A = (float)c0; B = (float)c2; C = (float)c3;
}

// ---------------- device scratch ----------------
__device__ float         g_dA[NWORK];
__device__ float         g_dB[NWORK];
__device__ float         g_dC[NWORK];
__device__ float         g_dD[NWORK];
__device__ unsigned      g_maps[NWORK];
__device__ unsigned char g_entry[NWORK];
__device__ float         g_offs[NWORK];
__device__ int           g_hist[HISTN];

__device__ __forceinline__ int f1_of(float u, float A, float B, float C) {
    return (u < A) ? 0 : ((u < B) ? 2 : ((u < C) ? 3 : 0));
}
__device__ __forceinline__ int advance(int s, int f1) {
    return (s == 0) ? 1 : ((s == 1) ? f1 : 0);
}
__device__ __forceinline__ float invr_of(int s) {
    return (s == 0) ? c_invr[0] : ((s == 1) ? c_invr[1] : ((s == 2) ? c_invr[2] : c_invr[3]));
}

// ---------------- K0: zero histogram ----------------
__global__ void k_zero() {
    int i = blockIdx.x * blockDim.x + threadIdx.x;
    if (i < HISTN) g_hist[i] = 0;
}

// ---------------- K1: chunk transfer maps + dwell totals (4 cols/thread) ----------------
__global__ void __launch_bounds__(256) k_chunk(const float* __restrict__ ucat,
                                               const float* __restrict__ uexp) {
    int gid = blockIdx.x * blockDim.x + threadIdx.x;   // 0 .. NTHRD-1
    int c4  = gid & (NCOL4 - 1);
    int c   = gid >> 9;
    float A, B, C; get_thresholds(A, B, C);

    const float4* pc = (const float4*)(ucat + (size_t)c * CH * NCOL) + c4;
    const float4* pe = (const float4*)(uexp + (size_t)c * CH * NCOL) + c4;

    int   sA[4], sB[4], sC[4];
    float aA[4], aB[4], aT[4], g0[4];
    #pragma unroll
    for (int j = 0; j < 4; j++) {
        sA[j] = 0; sB[j] = 1; sC[j] = 0;
        aA[j] = 0.f; aB[j] = 0.f; aT[j] = 0.f; g0[j] = 0.f;
    }

    #pragma unroll 5
    for (int k = 0; k < CH; k++) {
        float4 v1 = pc[(size_t)k * NCOL4];
        float4 v2 = pe[(size_t)k * NCOL4];
        float u1a[4] = {v1.x, v1.y, v1.z, v1.w};
        float u2a[4] = {v2.x, v2.y, v2.z, v2.w};
        #pragma unroll
        for (int j = 0; j < 4; j++) {
            float g  = -__logf(1.0f - u2a[j]);
            int  f1  = f1_of(u1a[j], A, B, C);
            if (k == 0) {
                g0[j] = g;
            } else {
                aT[j] = fmaf(g, invr_of(sC[j]), aT[j]);
                sC[j] = advance(sC[j], f1);
            }
            aA[j] = fmaf(g, invr_of(sA[j]), aA[j]);
            aB[j] = fmaf(g, invr_of(sB[j]), aB[j]);
            sA[j] = advance(sA[j], f1);
            sB[j] = advance(sB[j], f1);
        }
    }

    int idx0 = c * NCOL + c4 * 4;
    float4 rA, rB, rC, rD; uint4 rM;
    rA.x=aA[0]; rA.y=aA[1]; rA.z=aA[2]; rA.w=aA[3];
    rB.x=aB[0]; rB.y=aB[1]; rB.z=aB[2]; rB.w=aB[3];
    rC.x=fmaf(g0[0],c_invr[2],aT[0]); rC.y=fmaf(g0[1],c_invr[2],aT[1]);
    rC.z=fmaf(g0[2],c_invr[2],aT[2]); rC.w=fmaf(g0[3],c_invr[2],aT[3]);
    rD.x=fmaf(g0[0],c_invr[3],aT[0]); rD.y=fmaf(g0[1],c_invr[3],aT[1]);
    rD.z=fmaf(g0[2],c_invr[3],aT[2]); rD.w=fmaf(g0[3],c_invr[3],aT[3]);
    rM.x=(unsigned)sA[0]|((unsigned)sB[0]<<8)|((unsigned)sC[0]<<16);
    rM.y=(unsigned)sA[1]|((unsigned)sB[1]<<8)|((unsigned)sC[1]<<16);
    rM.z=(unsigned)sA[2]|((unsigned)sB[2]<<8)|((unsigned)sC[2]<<16);
    rM.w=(unsigned)sA[3]|((unsigned)sB[3]<<8)|((unsigned)sC[3]<<16);
    *(float4*)&g_dA[idx0] = rA;
    *(float4*)&g_dB[idx0] = rB;
    *(float4*)&g_dC[idx0] = rC;
    *(float4*)&g_dD[idx0] = rD;
    *(uint4*)&g_maps[idx0] = rM;
}

// ---------------- K2: per-column scan over chunks ----------------
__global__ void __launch_bounds__(256) k_boundary() {
    int col = blockIdx.x * blockDim.x + threadIdx.x;   // 0..2047
    int s = 0;
    double t = 0.0;
    for (int c = 0; c < NCH; c++) {
        int idx = c * NCOL + col;
        g_entry[idx] = (unsigned char)s;
        g_offs[idx]  = (float)t;
        float dv = (s == 0) ? g_dA[idx]
                 : (s == 1) ? g_dB[idx]
                 : (s == 2) ? g_dC[idx]
                 :            g_dD[idx];
        t += (double)dv;
        unsigned m = g_maps[idx];
        int sh = (s < 2) ? s : 2;
        s = (int)((m >> (8 * sh)) & 3u);
    }
}

// searchsorted-left into bins[j] = (float)j * 0.002f, clamped to [0, NBINS]
__device__ __forceinline__ int bucketf(float t) {
    float jf = ceilf(t * 500.0f);
    int j = (int)jf;
    j = max(0, min(j, NBINS));
    while (j > 0      && (float)(j - 1) * 0.002f >= t) --j;
    while (j < NBINS  && (float)j       * 0.002f <  t) ++j;
    return j;
}

// ---------------- K3: final resolve (4 cols/thread) ----------------
__global__ void __launch_bounds__(256) k_main(const float* __restrict__ ucat,
                                              const float* __restrict__ uexp,
                                              float* __restrict__ phot,
                                              float* __restrict__ cum) {
    int gid = blockIdx.x * blockDim.x + threadIdx.x;   // 0 .. NTHRD-1
    int c4  = gid & (NCOL4 - 1);
    int c   = gid >> 9;
    float A, B, C; get_thresholds(A, B, C);

    const float4* pc = (const float4*)(ucat + (size_t)c * CH * NCOL) + c4;
    const float4* pe = (const float4*)(uexp + (size_t)c * CH * NCOL) + c4;
    float4* pp = (float4*)(phot + (size_t)c * CH * NCOL) + c4;
    float4* pt = (float4*)(cum  + (size_t)c * CH * NCOL) + c4;

    int idx0 = c * NCOL + c4 * 4;
    uchar4 e4 = *(const uchar4*)&g_entry[idx0];
    float4 o4 = *(const float4*)&g_offs[idx0];

    int   s[4]       = {e4.x, e4.y, e4.z, e4.w};
    float t[4]       = {o4.x, o4.y, o4.z, o4.w};
    int   run_bin[4] = {-1, -1, -1, -1};
    int   run_cnt[4] = {0, 0, 0, 0};
    int   nz = 0;

    #pragma unroll 5
    for (int k = 0; k < CH; k++) {
        float4 v1 = pc[(size_t)k * NCOL4];
        float4 v2 = pe[(size_t)k * NCOL4];
        float u1a[4] = {v1.x, v1.y, v1.z, v1.w};
        float u2a[4] = {v2.x, v2.y, v2.z, v2.w};
        float pv[4], tv[4];

        #pragma unroll
        for (int j = 0; j < 4; j++) {
            bool  ph = (s[j] == 0);
            float g  = -__logf(1.0f - u2a[j]);
            t[j] += g * invr_of(s[j]);
            pv[j] = ph ? 1.0f : 0.0f;
            tv[j] = t[j];

            if (ph) {
                int b = bucketf(t[j]);
                if (b == run_bin[j]) {
                    run_cnt[j]++;
                } else {
                    if (run_cnt[j]) atomicAdd(&g_hist[run_bin[j]], run_cnt[j]);
                    run_bin[j] = b; run_cnt[j] = 1;
                }
            } else {
                nz++;
            }
            s[j] = advance(s[j], f1_of(u1a[j], A, B, C));
        }

        float4 wp, wt;
        wp.x=pv[0]; wp.y=pv[1]; wp.z=pv[2]; wp.w=pv[3];
        wt.x=tv[0]; wt.y=tv[1]; wt.z=tv[2]; wt.w=tv[3];
        pp[(size_t)k * NCOL4] = wp;
        pt[(size_t)k * NCOL4] = wt;
    }
    #pragma unroll
    for (int j = 0; j < 4; j++)
        if (run_cnt[j]) atomicAdd(&g_hist[run_bin[j]], run_cnt[j]);

    // aggregate the heavily contended hist[0] (non-photon entries) per warp
    int tot = __reduce_add_sync(0xffffffffu, nz);
    if ((threadIdx.x & 31) == 0 && tot) atomicAdd(&g_hist[0], tot);
}

// ---------------- K4: int hist -> float32 output tail ----------------
__global__ void k_hist_out(float* __restrict__ out_hist) {
    int i = blockIdx.x * blockDim.x + threadIdx.x;
    if (i < HISTN) out_hist[i] = (float)g_hist[i];
}

// ---------------- launch ----------------
extern "C" void kernel_launch(void* const* d_in, const int* in_sizes, int n_in,
                              void* d_out, int out_size) {
    const float* ucat = (const float*)d_in[0];
    const float* uexp = (const float*)d_in[1];
    float* out = (float*)d_out;

    const size_t n_elem = (size_t)STEPS * NCOL;   // 40,960,000
    float* out_phot = out;
    float* out_cum  = out + n_elem;
    float* out_hist = out + 2 * n_elem;

    const int th = 256;
    const int work_blocks = NTHRD / th;           // 800
    const int hist_blocks = (HISTN + th - 1) / th;

    k_zero<<<hist_blocks, th>>>();
    k_chunk<<<work_blocks, th>>>(ucat, uexp);
    k_boundary<<<NCOL / th, th>>>();
    k_main<<<work_blocks, th>>>(ucat, uexp, out_phot, out_cum);
    k_hist_out<<<hist_blocks, th>>>(out_hist);
}

// round 8
// speedup vs baseline: 1.5008x; 1.5008x over previous
#include <cuda_runtime.h>
#include <cuda_bf16.h>
#include <math.h>

// ---------------- problem constants ----------------
#define STEPS 20000
#define NCOL  2048
#define CH    100           // steps per chunk
#define NCH   (STEPS/CH)    // 200 chunks
#define NWORK (NCH * NCOL)  // 409,600 chunk-threads
#define NBINS 200000
#define HISTN (NBINS + 1)

#define R1_SUM_D 123020000.0
__device__ __constant__ float c_invr[4] = {
    1.0f / 1.0e6f, (float)(1.0 / R1_SUM_D), 1.0f / 1.0e5f, (float)(1.0 / 0.2)
};

__device__ __forceinline__ void get_thresholds(float& A, float& B, float& C) {
    const double c0 = 50000000.0 / R1_SUM_D;
    const double c2 = c0 + 3000000.0 / R1_SUM_D;
    const double c3 = c2 + 20000.0 / R1_SUM_D;
    A = (float)c0; B = (float)c2; C = (float)c3;
}

// ---------------- device scratch ----------------
__device__ float4        g_dwl[NWORK];               // {dA,dB,dC,dD}
__device__ unsigned      g_maps[NWORK];              // end states (entry 0/1/2+3)
__device__ unsigned char g_entry[NWORK];
__device__ float         g_offs[NWORK];
__device__ unsigned char g_state[(size_t)STEPS * NCOL]; // packed per-step states
__device__ int           g_hist[HISTN];

__device__ __forceinline__ int f1_of(float u, float A, float B, float C) {
    return (u < A) ? 0 : ((u < B) ? 2 : ((u < C) ? 3 : 0));
}
__device__ __forceinline__ int advance(int s, int f1) {
    return (s == 0) ? 1 : ((s == 1) ? f1 : 0);
}
__device__ __forceinline__ float invr_of(int s) {
    return (s == 0) ? c_invr[0] : ((s == 1) ? c_invr[1] : ((s == 2) ? c_invr[2] : c_invr[3]));
}

// smallest j in [0,NBINS] with (float)j*0.002f >= t  (branchless, +-2 correction)
__device__ __forceinline__ int bucket_arith(float t) {
    int j = (int)ceilf(t * 500.0f);
    j = max(0, min(j, NBINS));
    j += (j < NBINS) && ((float)j * 0.002f < t);
    j += (j < NBINS) && ((float)j * 0.002f < t);
    j -= (j > 0) && ((float)(j - 1) * 0.002f >= t);
    j -= (j > 0) && ((float)(j - 1) * 0.002f >= t);
    return j;
}

// ---------------- K0: zero histogram ----------------
__global__ void k_zero() {
    int i = blockIdx.x * blockDim.x + threadIdx.x;
    if (i < HISTN) g_hist[i] = 0;
}

// ---------------- K1: chunk maps + dwell totals + per-step packed states ----------------
__global__ void __launch_bounds__(256) k_chunk(const float* __restrict__ ucat,
                                               const float* __restrict__ uexp) {
    int gid = blockIdx.x * blockDim.x + threadIdx.x;   // 0 .. NWORK-1
    int col = gid & (NCOL - 1);
    int c   = gid >> 11;
    float A, B, C; get_thresholds(A, B, C);

    const float* pc = ucat + (size_t)c * CH * NCOL + col;
    const float* pe = uexp + (size_t)c * CH * NCOL + col;
    unsigned char* ps = g_state + (size_t)c * CH * NCOL + col;

    // ---- peeled step 0 ----
    float u1 = pc[0], u2 = pe[0];
    ps[0] = (unsigned char)(0 | (1 << 2) | (0 << 4));  // sA=0, sB=1 (sC unused at k=0)
    float g0 = -__logf(1.0f - u2);
    int   f1 = f1_of(u1, A, B, C);
    float aA = g0 * c_invr[0];
    float aB = g0 * c_invr[1];
    float aT = 0.f;
    int sA = 1;        // advance(0,f1)
    int sB = f1;       // advance(1,f1)
    int sC = 0;        // trajC begins at time 1 in state 0

    // ---- steps 1..CH-1 (branchless body) ----
    #pragma unroll 4
    for (int k = 1; k < CH; k++) {
        float v1 = pc[(size_t)k * NCOL];
        float v2 = pe[(size_t)k * NCOL];
        ps[(size_t)k * NCOL] = (unsigned char)(sA | (sB << 2) | (sC << 4));
        float g  = -__logf(1.0f - v2);
        int  f   = f1_of(v1, A, B, C);
        aT = fmaf(g, invr_of(sC), aT);
        aA = fmaf(g, invr_of(sA), aA);
        aB = fmaf(g, invr_of(sB), aB);
        sC = advance(sC, f);
        sA = advance(sA, f);
        sB = advance(sB, f);
    }

    float4 d;
    d.x = aA;
    d.y = aB;
    d.z = fmaf(g0, c_invr[2], aT);
    d.w = fmaf(g0, c_invr[3], aT);
    g_dwl[gid]  = d;
    g_maps[gid] = (unsigned)sA | ((unsigned)sB << 8) | ((unsigned)sC << 16);
}

// ---------------- K2: per-column scan over chunks ----------------
__global__ void __launch_bounds__(256) k_boundary() {
    int col = blockIdx.x * blockDim.x + threadIdx.x;   // 0..2047
    int s = 0;
    double t = 0.0;
    for (int c = 0; c < NCH; c++) {
        int idx = c * NCOL + col;
        g_entry[idx] = (unsigned char)s;
        g_offs[idx]  = (float)t;
        float4 d = g_dwl[idx];
        float dv = (s == 0) ? d.x : (s == 1) ? d.y : (s == 2) ? d.z : d.w;
        t += (double)dv;
        unsigned m = g_maps[idx];
        int sh = (s < 2) ? s : 2;
        s = (int)((m >> (8 * sh)) & 3u);
    }
}

// ---------------- K3: final resolve: photons, cum_time, histogram ----------------
__global__ void __launch_bounds__(256) k_main(const float* __restrict__ uexp,
                                              float* __restrict__ phot,
                                              float* __restrict__ cum) {
    __shared__ float s_invr[4];
    if (threadIdx.x < 4) s_invr[threadIdx.x] = c_invr[threadIdx.x];
    __syncthreads();

    int gid = blockIdx.x * blockDim.x + threadIdx.x;   // 0 .. NWORK-1
    int col = gid & (NCOL - 1);
    int c   = gid >> 11;

    const float* pe = uexp + (size_t)c * CH * NCOL + col;
    const unsigned char* ps = g_state + (size_t)c * CH * NCOL + col;
    float* pp = phot + (size_t)c * CH * NCOL + col;
    float* pt = cum  + (size_t)c * CH * NCOL + col;

    int   e = (int)g_entry[gid];
    float t = g_offs[gid];
    int   shift = 2 * min(e, 2);

    int   j = bucket_arith(t);
    float edge = (float)j * 0.002f;
    int   run_cnt = 0, nz = 0;

    // ---- peeled step 0: state is the entry state exactly ----
    {
        float u2 = pe[0];
        float g  = -__logf(1.0f - u2);
        t += g * s_invr[e];
        bool ph = (e == 0);
        pp[0] = ph ? 1.0f : 0.0f;
        pt[0] = t;
        if (ph) {
            if (t > edge) {
                if (run_cnt) atomicAdd(&g_hist[j], run_cnt);
                j = bucket_arith(t); edge = (float)j * 0.002f; run_cnt = 1;
            } else run_cnt++;
        } else nz++;
    }

    // ---- steps 1..CH-1: state comes from memory (no recurrence) ----
    #pragma unroll 4
    for (int k = 1; k < CH; k++) {
        float u2 = pe[(size_t)k * NCOL];
        int   s  = ((int)ps[(size_t)k * NCOL] >> shift) & 3;
        float g  = -__logf(1.0f - u2);
        t += g * s_invr[s];
        bool ph = (s == 0);
        pp[(size_t)k * NCOL] = ph ? 1.0f : 0.0f;
        pt[(size_t)k * NCOL] = t;
        if (ph) {
            if (t > edge) {                        // rare: bin crossing
                if (run_cnt) atomicAdd(&g_hist[j], run_cnt);
                j = bucket_arith(t); edge = (float)j * 0.002f; run_cnt = 1;
            } else run_cnt++;
        } else nz++;
    }
    if (run_cnt) atomicAdd(&g_hist[j], run_cnt);

    // aggregate the heavily contended hist[0] (non-photon entries) per warp
    int tot = __reduce_add_sync(0xffffffffu, nz);
    if ((threadIdx.x & 31) == 0 && tot) atomicAdd(&g_hist[0], tot);
}

// ---------------- K4: int hist -> float32 output tail ----------------
__global__ void k_hist_out(float* __restrict__ out_hist) {
    int i = blockIdx.x * blockDim.x + threadIdx.x;
    if (i < HISTN) out_hist[i] = (float)g_hist[i];
}

// ---------------- launch ----------------
extern "C" void kernel_launch(void* const* d_in, const int* in_sizes, int n_in,
                              void* d_out, int out_size) {
    const float* ucat = (const float*)d_in[0];
    const float* uexp = (const float*)d_in[1];
    float* out = (float*)d_out;

    const size_t n_elem = (size_t)STEPS * NCOL;   // 40,960,000
    float* out_phot = out;
    float* out_cum  = out + n_elem;
    float* out_hist = out + 2 * n_elem;

    const int th = 256;
    const int work_blocks = NWORK / th;           // 1600
    const int hist_blocks = (HISTN + th - 1) / th;

    k_zero<<<hist_blocks, th>>>();
    k_chunk<<<work_blocks, th>>>(ucat, uexp);
    k_boundary<<<NCOL / th, th>>>();
    k_main<<<work_blocks, th>>>(uexp, out_phot, out_cum);
    k_hist_out<<<hist_blocks, th>>>(out_hist);
}

// round 9
// speedup vs baseline: 1.7082x; 1.1382x over previous
#include <cuda_runtime.h>
#include <cuda_bf16.h>
#include <math.h>

// ---------------- problem constants ----------------
#define STEPS 20000
#define NCOL  2048
#define CH    100           // steps per chunk
#define NCH   (STEPS/CH)    // 200 chunks
#define NWORK (NCH * NCOL)
#define NBINS 200000
#define HISTN (NBINS + 1)
#define G     5             // prefetch group size
#define NG    (CH / G)      // 20 groups

#define R1_SUM_D 123020000.0
__device__ __constant__ float c_invr[4] = {
    1.0f / 1.0e6f, (float)(1.0 / R1_SUM_D), 1.0f / 1.0e5f, (float)(1.0 / 0.2)
};

__device__ __forceinline__ void get_thresholds(float& A, float& B, float& C) {
    const double c0 = 50000000.0 / R1_SUM_D;
    const double c2 = c0 + 3000000.0 / R1_SUM_D;
    const double c3 = c2 + 20000.0 / R1_SUM_D;
    A = (float)c0; B = (float)c2; C = (float)c3;
}

// ---------------- device scratch ----------------
__device__ float4        g_dwl[NWORK];               // {dA,dB,dC,dD}
__device__ unsigned      g_maps[NWORK];
__device__ unsigned char g_entry[NWORK];
__device__ float         g_offs[NWORK];
__device__ unsigned char g_state[(size_t)STEPS * NCOL]; // 4x 2-bit states per step
__device__ int           g_hist[HISTN];

__device__ __forceinline__ int f1_of(float u, float A, float B, float C) {
    return (u < A) ? 0 : ((u < B) ? 2 : ((u < C) ? 3 : 0));
}
__device__ __forceinline__ int advance(int s, int f1) {
    return (s == 0) ? 1 : ((s == 1) ? f1 : 0);
}
__device__ __forceinline__ float invr_of(int s) {
    return (s == 0) ? c_invr[0] : ((s == 1) ? c_invr[1] : ((s == 2) ? c_invr[2] : c_invr[3]));
}

// smallest j in [0,NBINS] with (float)j*0.002f >= t  (branchless +-2 correction)
__device__ __forceinline__ int bucket_arith(float t) {
    int j = (int)ceilf(t * 500.0f);
    j = max(0, min(j, NBINS));
    j += (j < NBINS) && ((float)j * 0.002f < t);
    j += (j < NBINS) && ((float)j * 0.002f < t);
    j -= (j > 0) && ((float)(j - 1) * 0.002f >= t);
    j -= (j > 0) && ((float)(j - 1) * 0.002f >= t);
    return j;
}

// ---------------- K0: zero histogram ----------------
__global__ void k_zero() {
    int i = blockIdx.x * blockDim.x + threadIdx.x;
    if (i < HISTN) g_hist[i] = 0;
}

// ---------------- K1: chunk maps + dwell totals + packed per-step states ----------------
__global__ void __launch_bounds__(256) k_chunk(const float* __restrict__ ucat,
                                               const float* __restrict__ uexp) {
    int gid = blockIdx.x * blockDim.x + threadIdx.x;
    int col = gid & (NCOL - 1);
    int c   = gid >> 11;
    float A, B, C; get_thresholds(A, B, C);

    const float* pc = ucat + (size_t)c * CH * NCOL + col;
    const float* pe = uexp + (size_t)c * CH * NCOL + col;
    unsigned char* ps = g_state + (size_t)c * CH * NCOL + col;

    int   sA = 0, sB = 1, sC = 0;
    float aA = 0.f, aB = 0.f, aT = 0.f, g0 = 0.f;

    float b1[2][G], b2[2][G];
    #pragma unroll
    for (int jj = 0; jj < G; jj++) {
        b1[0][jj] = pc[(size_t)jj * NCOL];
        b2[0][jj] = pe[(size_t)jj * NCOL];
    }

    #pragma unroll
    for (int g = 0; g < NG; g++) {
        const int cur = g & 1, nxt = cur ^ 1;
        if (g + 1 < NG) {
            #pragma unroll
            for (int jj = 0; jj < G; jj++) {
                b1[nxt][jj] = pc[(size_t)((g + 1) * G + jj) * NCOL];
                b2[nxt][jj] = pe[(size_t)((g + 1) * G + jj) * NCOL];
            }
        }
        #pragma unroll
        for (int jj = 0; jj < G; jj++) {
            const int k = g * G + jj;
            float u1 = b1[cur][jj];
            float u2 = b2[cur][jj];
            float gg = -__logf(1.0f - u2);
            int   f  = f1_of(u1, A, B, C);
            if (k == 0) {
                ps[0] = (unsigned char)0xE4;     // identity map: entry e -> state e
                g0 = gg;
                aA = gg * c_invr[0];
                aB = gg * c_invr[1];
                sA = 1; sB = f; sC = 0;
            } else {
                ps[(size_t)k * NCOL] =
                    (unsigned char)(sA | (sB << 2) | (sC << 4) | (sC << 6));
                aT = fmaf(gg, invr_of(sC), aT);
                aA = fmaf(gg, invr_of(sA), aA);
                aB = fmaf(gg, invr_of(sB), aB);
                sC = advance(sC, f);
                sA = advance(sA, f);
                sB = advance(sB, f);
            }
        }
    }

    float4 d;
    d.x = aA;
    d.y = aB;
    d.z = fmaf(g0, c_invr[2], aT);
    d.w = fmaf(g0, c_invr[3], aT);
    g_dwl[gid]  = d;
    g_maps[gid] = (unsigned)sA | ((unsigned)sB << 8) | ((unsigned)sC << 16);
}

// ---------------- K2: per-column scan over chunks ----------------
__global__ void __launch_bounds__(256) k_boundary() {
    int col = blockIdx.x * blockDim.x + threadIdx.x;   // 0..2047
    int s = 0;
    double t = 0.0;
    for (int c = 0; c < NCH; c++) {
        int idx = c * NCOL + col;
        g_entry[idx] = (unsigned char)s;
        g_offs[idx]  = (float)t;
        float4 d = g_dwl[idx];
        float dv = (s == 0) ? d.x : (s == 1) ? d.y : (s == 2) ? d.z : d.w;
        t += (double)dv;
        unsigned m = g_maps[idx];
        int sh = (s < 2) ? s : 2;
        s = (int)((m >> (8 * sh)) & 3u);
    }
}

// ---------------- K3: final resolve: photons, cum_time, histogram ----------------
__global__ void __launch_bounds__(256) k_main(const float* __restrict__ uexp,
                                              float* __restrict__ phot,
                                              float* __restrict__ cum) {
    __shared__ float s_invr[4];
    if (threadIdx.x < 4) s_invr[threadIdx.x] = c_invr[threadIdx.x];
    __syncthreads();

    int gid = blockIdx.x * blockDim.x + threadIdx.x;
    int col = gid & (NCOL - 1);
    int c   = gid >> 11;

    const float*         pe = uexp + (size_t)c * CH * NCOL + col;
    const unsigned char* ps = g_state + (size_t)c * CH * NCOL + col;
    float* pp = phot + (size_t)c * CH * NCOL + col;
    float* pt = cum  + (size_t)c * CH * NCOL + col;

    int   e     = (int)g_entry[gid];
    float t     = g_offs[gid];
    int   shift = 2 * e;                       // uniform: works for e=0..3

    int   j = bucket_arith(t);
    float edge = (float)j * 0.002f;
    int   run_cnt = 0, nz = 0;

    float ub[2][G]; int sb[2][G];
    #pragma unroll
    for (int jj = 0; jj < G; jj++) {
        ub[0][jj] = pe[(size_t)jj * NCOL];
        sb[0][jj] = (int)ps[(size_t)jj * NCOL];
    }

    #pragma unroll
    for (int g = 0; g < NG; g++) {
        const int cur = g & 1, nxt = cur ^ 1;
        if (g + 1 < NG) {
            #pragma unroll
            for (int jj = 0; jj < G; jj++) {
                ub[nxt][jj] = pe[(size_t)((g + 1) * G + jj) * NCOL];
                sb[nxt][jj] = (int)ps[(size_t)((g + 1) * G + jj) * NCOL];
            }
        }
        #pragma unroll
        for (int jj = 0; jj < G; jj++) {
            const int k = g * G + jj;
            float u2 = ub[cur][jj];
            int   s  = (sb[cur][jj] >> shift) & 3;
            float gg = -__logf(1.0f - u2);
            t += gg * s_invr[s];
            bool ph = (s == 0);
            pp[(size_t)k * NCOL] = ph ? 1.0f : 0.0f;
            pt[(size_t)k * NCOL] = t;
            if (ph) {
                if (t > edge) {                // rare: bin crossing
                    if (run_cnt) atomicAdd(&g_hist[j], run_cnt);
                    j = bucket_arith(t); edge = (float)j * 0.002f; run_cnt = 1;
                } else run_cnt++;
            } else nz++;
        }
    }
    if (run_cnt) atomicAdd(&g_hist[j], run_cnt);

    int tot = __reduce_add_sync(0xffffffffu, nz);
    if ((threadIdx.x & 31) == 0 && tot) atomicAdd(&g_hist[0], tot);
}

// ---------------- K4: int hist -> float32 output tail ----------------
__global__ void k_hist_out(float* __restrict__ out_hist) {
    int i = blockIdx.x * blockDim.x + threadIdx.x;
    if (i < HISTN) out_hist[i] = (float)g_hist[i];
}

// ---------------- launch ----------------
extern "C" void kernel_launch(void* const* d_in, const int* in_sizes, int n_in,
                              void* d_out, int out_size) {
    const float* ucat = (const float*)d_in[0];
    const float* uexp = (const float*)d_in[1];
    float* out = (float*)d_out;

    const size_t n_elem = (size_t)STEPS * NCOL;
    float* out_phot = out;
    float* out_cum  = out + n_elem;
    float* out_hist = out + 2 * n_elem;

    const int th = 256;
    const int work_blocks = NWORK / th;           // 1600
    const int hist_blocks = (HISTN + th - 1) / th;

    k_zero<<<hist_blocks, th>>>();
    k_chunk<<<work_blocks, th>>>(ucat, uexp);
    k_boundary<<<NCOL / th, th>>>();
    k_main<<<work_blocks, th>>>(uexp, out_phot, out_cum);
    k_hist_out<<<hist_blocks, th>>>(out_hist);
}

// round 10
// speedup vs baseline: 1.9374x; 1.1342x over previous
#include <cuda_runtime.h>
#include <cuda_bf16.h>
#include <math.h>

// ---------------- problem constants ----------------
#define STEPS 20000
#define NCOL  2048
#define CH    100           // steps per chunk
#define NCH   (STEPS/CH)    // 200 chunks
#define NWORK (NCH * NCOL)
#define NBINS 200000
#define HISTN (NBINS + 1)
#define G     5             // prefetch group size (steps)
#define NG    (CH / G)      // 20 groups
#define BG    10            // boundary prefetch group (chunks)

#define R1_SUM_D 123020000.0
__device__ __constant__ float c_invr[4] = {
    1.0f / 1.0e6f, (float)(1.0 / R1_SUM_D), 1.0f / 1.0e5f, (float)(1.0 / 0.2)
};

__device__ __forceinline__ void get_thresholds(float& A, float& B, float& C) {
    const double c0 = 50000000.0 / R1_SUM_D;
    const double c2 = c0 + 3000000.0 / R1_SUM_D;
    const double c3 = c2 + 20000.0 / R1_SUM_D;
    A = (float)c0; B = (float)c2; C = (float)c3;
}

// ---- pinned (un-sinkable) loads: asm volatile cannot be reordered by ptxas ----
__device__ __forceinline__ float vldg_f32(const float* p) {
    float v; asm volatile("ld.global.nc.f32 %0, [%1];" : "=f"(v) : "l"(p)); return v;
}
__device__ __forceinline__ int vldg_u8(const unsigned char* p) {
    unsigned v; asm volatile("ld.global.nc.u8 %0, [%1];" : "=r"(v) : "l"(p)); return (int)v;
}
__device__ __forceinline__ float4 vldg_f4(const float4* p) {
    float4 v;
    asm volatile("ld.global.nc.v4.f32 {%0,%1,%2,%3}, [%4];"
                 : "=f"(v.x), "=f"(v.y), "=f"(v.z), "=f"(v.w) : "l"(p));
    return v;
}
__device__ __forceinline__ unsigned vldg_u32(const unsigned* p) {
    unsigned v; asm volatile("ld.global.nc.u32 %0, [%1];" : "=r"(v) : "l"(p)); return v;
}

// ---------------- device scratch ----------------
__device__ float4        g_dwl[NWORK];               // {dA,dB,dC,dD}
__device__ unsigned      g_maps[NWORK];
__device__ unsigned char g_entry[NWORK];
__device__ float         g_offs[NWORK];
__device__ unsigned char g_state[(size_t)STEPS * NCOL]; // 4x 2-bit states per step
__device__ int           g_hist[HISTN];

__device__ __forceinline__ int f1_of(float u, float A, float B, float C) {
    return (u < A) ? 0 : ((u < B) ? 2 : ((u < C) ? 3 : 0));
}
__device__ __forceinline__ int advance(int s, int f1) {
    return (s == 0) ? 1 : ((s == 1) ? f1 : 0);
}
__device__ __forceinline__ float invr_of(int s) {
    return (s == 0) ? c_invr[0] : ((s == 1) ? c_invr[1] : ((s == 2) ? c_invr[2] : c_invr[3]));
}

// smallest j in [0,NBINS] with (float)j*0.002f >= t  (branchless +-2 correction)
__device__ __forceinline__ int bucket_arith(float t) {
    int j = (int)ceilf(t * 500.0f);
    j = max(0, min(j, NBINS));
    j += (j < NBINS) && ((float)j * 0.002f < t);
    j += (j < NBINS) && ((float)j * 0.002f < t);
    j -= (j > 0) && ((float)(j - 1) * 0.002f >= t);
    j -= (j > 0) && ((float)(j - 1) * 0.002f >= t);
    return j;
}

// ---------------- K0: zero histogram ----------------
__global__ void k_zero() {
    int i = blockIdx.x * blockDim.x + threadIdx.x;
    if (i < HISTN) g_hist[i] = 0;
}

// ---------------- K1: chunk maps + dwell totals + packed per-step states ----------------
__global__ void __launch_bounds__(256) k_chunk(const float* __restrict__ ucat,
                                               const float* __restrict__ uexp) {
    int gid = blockIdx.x * blockDim.x + threadIdx.x;
    int col = gid & (NCOL - 1);
    int c   = gid >> 11;
    float A, B, C; get_thresholds(A, B, C);

    const float* pc = ucat + (size_t)c * CH * NCOL + col;
    const float* pe = uexp + (size_t)c * CH * NCOL + col;
    unsigned char* ps = g_state + (size_t)c * CH * NCOL + col;

    int   sA = 0, sB = 1, sC = 0;
    float aA = 0.f, aB = 0.f, aT = 0.f, g0 = 0.f;

    float b1[2][G], b2[2][G];
    #pragma unroll
    for (int jj = 0; jj < G; jj++) {
        b1[0][jj] = vldg_f32(pc + (size_t)jj * NCOL);
        b2[0][jj] = vldg_f32(pe + (size_t)jj * NCOL);
    }

    #pragma unroll
    for (int g = 0; g < NG; g++) {
        const int cur = g & 1, nxt = cur ^ 1;
        if (g + 1 < NG) {
            #pragma unroll
            for (int jj = 0; jj < G; jj++) {
                b1[nxt][jj] = vldg_f32(pc + (size_t)((g + 1) * G + jj) * NCOL);
                b2[nxt][jj] = vldg_f32(pe + (size_t)((g + 1) * G + jj) * NCOL);
            }
        }
        #pragma unroll
        for (int jj = 0; jj < G; jj++) {
            const int k = g * G + jj;
            float u1 = b1[cur][jj];
            float u2 = b2[cur][jj];
            float gg = -__logf(1.0f - u2);
            int   f  = f1_of(u1, A, B, C);
            if (k == 0) {
                ps[0] = (unsigned char)0xE4;     // identity map: entry e -> state e
                g0 = gg;
                aA = gg * c_invr[0];
                aB = gg * c_invr[1];
                sA = 1; sB = f; sC = 0;
            } else {
                ps[(size_t)k * NCOL] =
                    (unsigned char)(sA | (sB << 2) | (sC << 4) | (sC << 6));
                aT = fmaf(gg, invr_of(sC), aT);
                aA = fmaf(gg, invr_of(sA), aA);
                aB = fmaf(gg, invr_of(sB), aB);
                sC = advance(sC, f);
                sA = advance(sA, f);
                sB = advance(sB, f);
            }
        }
    }

    float4 d;
    d.x = aA;
    d.y = aB;
    d.z = fmaf(g0, c_invr[2], aT);
    d.w = fmaf(g0, c_invr[3], aT);
    g_dwl[gid]  = d;
    g_maps[gid] = (unsigned)sA | ((unsigned)sB << 8) | ((unsigned)sC << 16);
}

// ---------------- K2: per-column scan over chunks (prefetched) ----------------
__global__ void __launch_bounds__(256) k_boundary() {
    int col = blockIdx.x * blockDim.x + threadIdx.x;   // 0..2047
    int s = 0;
    double t = 0.0;

    float4   bd[2][BG];
    unsigned bm[2][BG];
    #pragma unroll
    for (int jj = 0; jj < BG; jj++) {
        bd[0][jj] = vldg_f4(&g_dwl[jj * NCOL + col]);
        bm[0][jj] = vldg_u32(&g_maps[jj * NCOL + col]);
    }

    #pragma unroll
    for (int g = 0; g < NCH / BG; g++) {
        const int cur = g & 1, nxt = cur ^ 1;
        if (g + 1 < NCH / BG) {
            #pragma unroll
            for (int jj = 0; jj < BG; jj++) {
                bd[nxt][jj] = vldg_f4(&g_dwl[((g + 1) * BG + jj) * NCOL + col]);
                bm[nxt][jj] = vldg_u32(&g_maps[((g + 1) * BG + jj) * NCOL + col]);
            }
        }
        #pragma unroll
        for (int jj = 0; jj < BG; jj++) {
            const int c = g * BG + jj;
            int idx = c * NCOL + col;
            g_entry[idx] = (unsigned char)s;
            g_offs[idx]  = (float)t;
            float4 d = bd[cur][jj];
            float dv = (s == 0) ? d.x : (s == 1) ? d.y : (s == 2) ? d.z : d.w;
            t += (double)dv;
            unsigned m = bm[cur][jj];
            int sh = (s < 2) ? s : 2;
            s = (int)((m >> (8 * sh)) & 3u);
        }
    }
}

// ---------------- K3: final resolve: photons, cum_time, histogram ----------------
__global__ void __launch_bounds__(256) k_main(const float* __restrict__ uexp,
                                              float* __restrict__ phot,
                                              float* __restrict__ cum) {
    __shared__ float s_invr[4];
    if (threadIdx.x < 4) s_invr[threadIdx.x] = c_invr[threadIdx.x];
    __syncthreads();

    int gid = blockIdx.x * blockDim.x + threadIdx.x;
    int col = gid & (NCOL - 1);
    int c   = gid >> 11;

    const float*         pe = uexp + (size_t)c * CH * NCOL + col;
    const unsigned char* ps = g_state + (size_t)c * CH * NCOL + col;
    float* pp = phot + (size_t)c * CH * NCOL + col;
    float* pt = cum  + (size_t)c * CH * NCOL + col;

    int   e     = (int)g_entry[gid];
    float t     = g_offs[gid];
    int   shift = 2 * e;

    int   j = bucket_arith(t);
    float edge = (float)j * 0.002f;
    int   run_cnt = 0, nz = 0;

    float ub[2][G]; int sb[2][G];
    #pragma unroll
    for (int jj = 0; jj < G; jj++) {
        ub[0][jj] = vldg_f32(pe + (size_t)jj * NCOL);
        sb[0][jj] = vldg_u8(ps + (size_t)jj * NCOL);
    }

    #pragma unroll
    for (int g = 0; g < NG; g++) {
        const int cur = g & 1, nxt = cur ^ 1;
        if (g + 1 < NG) {
            #pragma unroll
            for (int jj = 0; jj < G; jj++) {
                ub[nxt][jj] = vldg_f32(pe + (size_t)((g + 1) * G + jj) * NCOL);
                sb[nxt][jj] = vldg_u8(ps + (size_t)((g + 1) * G + jj) * NCOL);
            }
        }
        #pragma unroll
        for (int jj = 0; jj < G; jj++) {
            const int k = g * G + jj;
            float u2 = ub[cur][jj];
            int   s  = (sb[cur][jj] >> shift) & 3;
            float gg = -__logf(1.0f - u2);
            t += gg * s_invr[s];
            bool ph = (s == 0);
            __stcs(pp + (size_t)k * NCOL, ph ? 1.0f : 0.0f);
            __stcs(pt + (size_t)k * NCOL, t);
            if (ph) {
                if (t > edge) {                // rare: bin crossing
                    if (run_cnt) atomicAdd(&g_hist[j], run_cnt);
                    j = bucket_arith(t); edge = (float)j * 0.002f; run_cnt = 1;
                } else run_cnt++;
            } else nz++;
        }
    }
    if (run_cnt) atomicAdd(&g_hist[j], run_cnt);

    int tot = __reduce_add_sync(0xffffffffu, nz);
    if ((threadIdx.x & 31) == 0 && tot) atomicAdd(&g_hist[0], tot);
}

// ---------------- K4: int hist -> float32 output tail ----------------
__global__ void k_hist_out(float* __restrict__ out_hist) {
    int i = blockIdx.x * blockDim.x + threadIdx.x;
    if (i < HISTN) out_hist[i] = (float)g_hist[i];
}

// ---------------- launch ----------------
extern "C" void kernel_launch(void* const* d_in, const int* in_sizes, int n_in,
                              void* d_out, int out_size) {
    const float* ucat = (const float*)d_in[0];
    const float* uexp = (const float*)d_in[1];
    float* out = (float*)d_out;

    const size_t n_elem = (size_t)STEPS * NCOL;
    float* out_phot = out;
    float* out_cum  = out + n_elem;
    float* out_hist = out + 2 * n_elem;

    const int th = 256;
    const int work_blocks = NWORK / th;           // 1600
    const int hist_blocks = (HISTN + th - 1) / th;

    k_zero<<<hist_blocks, th>>>();
    k_chunk<<<work_blocks, th>>>(ucat, uexp);
    k_boundary<<<NCOL / th, th>>>();
    k_main<<<work_blocks, th>>>(uexp, out_phot, out_cum);
    k_hist_out<<<hist_blocks, th>>>(out_hist);
}